// round 11
// baseline (speedup 1.0000x reference)
#include <cuda_runtime.h>
#include <cuda_fp16.h>
#include <cstdint>

#define BSZ    2
#define SEQ    2048
#define DMODEL 1024
#define NHEAD  16
#define DKH    64
#define MROWS  (BSZ * SEQ)   // 4096

// Scratch (allocation-free rule: __device__ globals). All fp16.
__device__ __half g_xh[MROWS * DMODEL];          // x in half
__device__ __half g_wh[4 * DMODEL * DMODEL];     // Wq,Wk,Wv,Wo in half
__device__ __half g_q[MROWS * DMODEL];           // q (scaled)
__device__ __half g_k[MROWS * DMODEL];           // k
__device__ __half g_v[MROWS * DMODEL];           // vt[b][h][64][2048]
__device__ __half g_a[MROWS * DMODEL];           // attention output (half)

// ---------------------------------------------------------------------------
// helpers (sm_80+ features only — the build targets plain sm_103)
// ---------------------------------------------------------------------------
__device__ __forceinline__ void mma_f16(
    float& d0, float& d1, float& d2, float& d3,
    uint32_t a0, uint32_t a1, uint32_t a2, uint32_t a3,
    uint32_t b0, uint32_t b1)
{
    asm volatile(
        "mma.sync.aligned.m16n8k16.row.col.f32.f16.f16.f32 "
        "{%0,%1,%2,%3}, {%4,%5,%6,%7}, {%8,%9}, {%0,%1,%2,%3};"
        : "+f"(d0), "+f"(d1), "+f"(d2), "+f"(d3)
        : "r"(a0), "r"(a1), "r"(a2), "r"(a3), "r"(b0), "r"(b1));
}

__device__ __forceinline__ void ldsm_x4(
    uint32_t& r0, uint32_t& r1, uint32_t& r2, uint32_t& r3, uint32_t addr)
{
    asm volatile("ldmatrix.sync.aligned.m8n8.x4.shared.b16 {%0,%1,%2,%3}, [%4];"
                 : "=r"(r0), "=r"(r1), "=r"(r2), "=r"(r3) : "r"(addr));
}

__device__ __forceinline__ uint32_t smem_u32(const void* p) {
    uint32_t a;
    asm("{ .reg .u64 t; cvta.to.shared.u64 t, %1; cvt.u32.u64 %0, t; }"
        : "=r"(a) : "l"(p));
    return a;
}

__device__ __forceinline__ void cp16(uint32_t dst, const void* src) {
    asm volatile("cp.async.ca.shared.global [%0], [%1], 16;"
                 :: "r"(dst), "l"(src) : "memory");
}
#define CP_COMMIT() asm volatile("cp.async.commit_group;" ::: "memory")
#define CP_WAIT0()  asm volatile("cp.async.wait_group 0;" ::: "memory")
#define CP_WAIT1()  asm volatile("cp.async.wait_group 1;" ::: "memory")

// ---------------------------------------------------------------------------
// Prepass: fp32 -> fp16 conversion (producer-side; enables cp.async loaders)
// ---------------------------------------------------------------------------
__global__ __launch_bounds__(256) void f2h(
    const float* __restrict__ s, __half* __restrict__ d, int n)
{
    const int i = (blockIdx.x * 256 + threadIdx.x) * 8;
    if (i < n) {
        float4 a = *(const float4*)(s + i);
        float4 b = *(const float4*)(s + i + 4);
        union { __half2 h[4]; uint4 u; } u;
        u.h[0] = __floats2half2_rn(a.x, a.y);
        u.h[1] = __floats2half2_rn(a.z, a.w);
        u.h[2] = __floats2half2_rn(b.x, b.y);
        u.h[3] = __floats2half2_rn(b.z, b.w);
        *(uint4*)(d + i) = u.u;
    }
}

__global__ __launch_bounds__(256) void f2h4(
    const float* __restrict__ w0, const float* __restrict__ w1,
    const float* __restrict__ w2, const float* __restrict__ w3,
    __half* __restrict__ d)
{
    const float* srcs[4] = {w0, w1, w2, w3};
    const float* s = srcs[blockIdx.y];
    __half* dd = d + (size_t)blockIdx.y * DMODEL * DMODEL;
    const int i = (blockIdx.x * 256 + threadIdx.x) * 8;
    float4 a = *(const float4*)(s + i);
    float4 b = *(const float4*)(s + i + 4);
    union { __half2 h[4]; uint4 u; } u;
    u.h[0] = __floats2half2_rn(a.x, a.y);
    u.h[1] = __floats2half2_rn(a.z, a.w);
    u.h[2] = __floats2half2_rn(b.x, b.y);
    u.h[3] = __floats2half2_rn(b.z, b.w);
    *(uint4*)(dd + i) = u.u;
}

// ---------------------------------------------------------------------------
// fp16 GEMM NT body: C[m,n] = sum_k A[m,k] * W[n,k]   (half in; fp32 accum)
// 128x128 tile, BK=32, 8 warps (4Mx2N), cp.async 3-stage ring, ldmatrix frags.
// Smem per stage 16KB: A chunk-major [4][128][16B] at 0; B same at 8192.
// Output modes: 0 = fp32; 1 = half (scaled); 2 = half transposed per-head.
// ---------------------------------------------------------------------------
#define GEMM_SMEM (3 * 16384)   // 49152 B

__device__ __forceinline__ void gemm_body(
    const __half* __restrict__ A, const __half* __restrict__ W,
    void* __restrict__ Cv, float oscale, int mode, char* smg)
{
    const int tid  = threadIdx.x;
    const int wid  = tid >> 5;
    const int lane = tid & 31;
    const int wm   = wid & 3;
    const int wn   = wid >> 2;
    const int m0 = blockIdx.y * 128;
    const int n0 = blockIdx.x * 128;
    const uint32_t smb = smem_u32(smg);

    // loader: row = tid>>1 (0..127), chunks (tid&1)*2 and +1 (32B contiguous)
    const int lr  = tid >> 1;
    const int lc2 = (tid & 1) * 2;
    const __half* Ag = A + (size_t)(m0 + lr) * DMODEL + lc2 * 8;
    const __half* Wg = W + (size_t)(n0 + lr) * DMODEL + lc2 * 8;
    const uint32_t sA0 = lc2 * 2048 + lr * 16;
    const uint32_t sA1 = (lc2 + 1) * 2048 + lr * 16;

    float acc[2][8][4];
#pragma unroll
    for (int i = 0; i < 2; i++)
#pragma unroll
        for (int j = 0; j < 8; j++)
#pragma unroll
            for (int r = 0; r < 4; r++) acc[i][j][r] = 0.0f;

    const int NCH = DMODEL / 32;   // 32

    // prologue: stages 0 and 1
#pragma unroll
    for (int s = 0; s < 2; s++) {
        const uint32_t st = smb + s * 16384;
        const int k0 = s * 32;
        cp16(st + sA0,        Ag + k0);
        cp16(st + sA1,        Ag + k0 + 8);
        cp16(st + 8192 + sA0, Wg + k0);
        cp16(st + 8192 + sA1, Wg + k0 + 8);
        CP_COMMIT();
    }

    for (int s = 0; s < NCH; s++) {
        if (s == NCH - 1) { CP_WAIT0(); } else { CP_WAIT1(); }
        __syncthreads();

        // issue stage s+2 (overwrites stage (s-1)%3; all warps past compute(s-1))
        if (s + 2 < NCH) {
            const uint32_t st = smb + ((s + 2) % 3) * 16384;
            const int k0 = (s + 2) * 32;
            cp16(st + sA0,        Ag + k0);
            cp16(st + sA1,        Ag + k0 + 8);
            cp16(st + 8192 + sA0, Wg + k0);
            cp16(st + 8192 + sA1, Wg + k0 + 8);
            CP_COMMIT();
        }

        const uint32_t st = smb + (s % 3) * 16384;
#pragma unroll
        for (int ks = 0; ks < 2; ks++) {
            uint32_t af[2][4];
            uint32_t bf[8][2];
#pragma unroll
            for (int mt = 0; mt < 2; mt++) {
                const uint32_t addr = st + (2 * ks + (lane >> 4)) * 2048
                                    + (wm * 32 + mt * 16 + (lane & 15)) * 16;
                ldsm_x4(af[mt][0], af[mt][1], af[mt][2], af[mt][3], addr);
            }
#pragma unroll
            for (int p = 0; p < 4; p++) {
                const uint32_t addr = st + 8192 + (2 * ks + ((lane >> 3) & 1)) * 2048
                                    + (wn * 64 + p * 16 + ((lane >> 4) << 3) + (lane & 7)) * 16;
                ldsm_x4(bf[2 * p][0], bf[2 * p][1], bf[2 * p + 1][0], bf[2 * p + 1][1], addr);
            }
#pragma unroll
            for (int mt = 0; mt < 2; mt++)
#pragma unroll
                for (int nt = 0; nt < 8; nt++)
                    mma_f16(acc[mt][nt][0], acc[mt][nt][1],
                            acc[mt][nt][2], acc[mt][nt][3],
                            af[mt][0], af[mt][1], af[mt][2], af[mt][3],
                            bf[nt][0], bf[nt][1]);
        }
    }

    const int g = lane >> 2, q = lane & 3;
#pragma unroll
    for (int mt = 0; mt < 2; mt++) {
        const int mrow = m0 + wm * 32 + mt * 16 + g;
#pragma unroll
        for (int nt = 0; nt < 8; nt++) {
            const int ncol = n0 + wn * 64 + nt * 8 + 2 * q;
            if (mode == 0) {
                float* C = (float*)Cv;
                *(float2*)(C + (size_t)mrow * DMODEL + ncol) =
                    make_float2(acc[mt][nt][0], acc[mt][nt][1]);
                *(float2*)(C + (size_t)(mrow + 8) * DMODEL + ncol) =
                    make_float2(acc[mt][nt][2], acc[mt][nt][3]);
            } else if (mode == 1) {
                __half2* C = (__half2*)Cv;
                C[((size_t)mrow * DMODEL + ncol) >> 1] =
                    __floats2half2_rn(acc[mt][nt][0] * oscale, acc[mt][nt][1] * oscale);
                C[((size_t)(mrow + 8) * DMODEL + ncol) >> 1] =
                    __floats2half2_rn(acc[mt][nt][2] * oscale, acc[mt][nt][3] * oscale);
            } else {
                // vt[((b*NHEAD + h)*64 + d) * SEQ + s]
                __half* C = (__half*)Cv;
                const int h = ncol >> 6, d = ncol & 63;
                const size_t hb = ((size_t)((mrow >> 11) * NHEAD + h) * 64);
                const int s0 = mrow & 2047;
                C[(hb + d)     * SEQ + s0]     = __float2half_rn(acc[mt][nt][0]);
                C[(hb + d + 1) * SEQ + s0]     = __float2half_rn(acc[mt][nt][1]);
                C[(hb + d)     * SEQ + s0 + 8] = __float2half_rn(acc[mt][nt][2]);
                C[(hb + d + 1) * SEQ + s0 + 8] = __float2half_rn(acc[mt][nt][3]);
            }
        }
    }
}

// Fused QKV: one launch, grid.z selects projection (tail-overlap across GEMMs)
__global__ __launch_bounds__(256, 2) void gemm_qkv(
    const __half* __restrict__ xh, const __half* __restrict__ wh,
    __half* __restrict__ qb, __half* __restrict__ kb, __half* __restrict__ vb,
    float qscale)
{
    extern __shared__ char smg[];
    const int z = blockIdx.z;
    const __half* W = wh + (size_t)z * DMODEL * DMODEL;
    void* C   = (z == 0) ? (void*)qb : (z == 1) ? (void*)kb : (void*)vb;
    const float sc = (z == 0) ? qscale : 1.0f;
    const int mode = (z == 2) ? 2 : 1;
    gemm_body(xh, W, C, sc, mode, smg);
}

__global__ __launch_bounds__(256, 2) void gemm_out(
    const __half* __restrict__ A, const __half* __restrict__ W,
    float* __restrict__ C)
{
    extern __shared__ char smg[];
    gemm_body(A, W, C, 1.0f, 0, smg);
}

// ---------------------------------------------------------------------------
// fp16 tensor-core flash attention (causal). BQ=128 (8 warps x m16), BKV=64.
// Q/K half [B*S][D] (head slices); V half transposed vt[b][h][64][2048].
// 2-stage cp.async ring; ONE barrier per tile; reversed qb (LPT).
// Output written as half (consumed by the Wo GEMM).
// ---------------------------------------------------------------------------
#define FH_LD        72
#define FH_PS_HALVES (128 * FH_LD)            // 9216
#define FH_STG_HALVES (2 * 64 * FH_LD)        // 9216 (K + V)
#define FA_SMEM ((FH_PS_HALVES + 2 * FH_STG_HALVES) * 2)   // 55296 B

__global__ __launch_bounds__(256, 2) void flash_attn_f16(
    const __half* __restrict__ Q, const __half* __restrict__ K,
    const __half* __restrict__ Vt, __half* __restrict__ O)
{
    extern __shared__ __half sh[];
    __half* Ps = sh;                          // 128 x 72 (Q staging, then P)

    const int tid  = threadIdx.x;
    const int w    = tid >> 5;
    const int lane = tid & 31;
    const int g    = lane >> 2;
    const int q    = lane & 3;
    const int qb = gridDim.x - 1 - blockIdx.x;   // reversed: longest first
    const int h  = blockIdx.y, b = blockIdx.z;
    const int q0 = qb * 128;
    const size_t baseh = (size_t)b * SEQ * DMODEL + (size_t)h * DKH;   // half idx
    const size_t vbase = ((size_t)(b * NHEAD + h)) * 64 * SEQ;         // vt half idx

    const uint32_t smb = smem_u32(sh);

    const int ntiles = 2 * qb + 2;

    // --- prologue: async-stage Q (128 rows x 128B) and KV tile 0 ---
    for (int i = tid; i < 128 * 8; i += 256) {
        const int r = i >> 3, c = (i & 7) * 8;             // halves
        cp16(smb + (r * FH_LD + c) * 2, Q + baseh + (size_t)(q0 + r) * DMODEL + c);
    }
    {
        const int lrk = tid >> 3, lck = (tid & 7) * 8;     // 32 rows x 8-half chunks
        const uint32_t kb0 = smb + FH_PS_HALVES * 2;
        const uint32_t vb0 = kb0 + 64 * FH_LD * 2;
#pragma unroll
        for (int j = 0; j < 2; j++) {
            const int r = lrk + 32 * j;
            cp16(kb0 + (r * FH_LD + lck) * 2, K + baseh + (size_t)r * DMODEL + lck);
            cp16(vb0 + (r * FH_LD + lck) * 2, Vt + vbase + (size_t)r * SEQ + lck);
        }
    }
    CP_COMMIT();
    CP_WAIT0();
    __syncthreads();

    // --- lift Q to register fragments: qf[ks][4], ks over dk (4 x k16) ---
    uint32_t qf[4][4];
    {
        const uint32_t* r0p = (const uint32_t*)Ps + (w * 16 + g) * 36;
        const uint32_t* r1p = r0p + 8 * 36;
#pragma unroll
        for (int ks = 0; ks < 4; ks++) {
            qf[ks][0] = r0p[ks * 8 + q];
            qf[ks][1] = r1p[ks * 8 + q];
            qf[ks][2] = r0p[ks * 8 + q + 4];
            qf[ks][3] = r1p[ks * 8 + q + 4];
        }
    }

    float m0 = -1e30f, m1 = -1e30f, l0 = 0.0f, l1 = 0.0f;
    float acc[8][4];
#pragma unroll
    for (int nt = 0; nt < 8; nt++)
#pragma unroll
        for (int r = 0; r < 4; r++) acc[nt][r] = 0.0f;

    const int rmin = q0 + w * 16;
    const int rmax = rmin + 15;

    for (int kb = 0; kb < ntiles; kb++) {
        const int kv0 = kb * 64;

        // --- issue cp.async for next tile into the other stage ---
        if (kb + 1 < ntiles) {
            const int lrk = tid >> 3, lck = (tid & 7) * 8;
            const uint32_t kbn = smb + (FH_PS_HALVES + ((kb + 1) & 1) * FH_STG_HALVES) * 2;
            const uint32_t vbn = kbn + 64 * FH_LD * 2;
#pragma unroll
            for (int j = 0; j < 2; j++) {
                const int r = lrk + 32 * j;
                cp16(kbn + (r * FH_LD + lck) * 2,
                     K + baseh + (size_t)(kv0 + 64 + r) * DMODEL + lck);
                cp16(vbn + (r * FH_LD + lck) * 2,
                     Vt + vbase + (size_t)r * SEQ + kv0 + 64 + lck);
            }
            CP_COMMIT();
        }

        const uint32_t* Ks32 = (const uint32_t*)(sh + FH_PS_HALVES + (kb & 1) * FH_STG_HALVES);
        const uint32_t* Vs32 = Ks32 + 64 * 36;   // V tile after full K tile

        if (kv0 <= rmax) {
            // --- S = Q @ K^T ---
            float sf[8][4];
#pragma unroll
            for (int nt = 0; nt < 8; nt++)
#pragma unroll
                for (int r = 0; r < 4; r++) sf[nt][r] = 0.0f;

#pragma unroll
            for (int ks = 0; ks < 4; ks++) {
#pragma unroll
                for (int nt = 0; nt < 8; nt++) {
                    const uint32_t* kr = Ks32 + (nt * 8 + g) * 36 + ks * 8;
                    mma_f16(sf[nt][0], sf[nt][1], sf[nt][2], sf[nt][3],
                            qf[ks][0], qf[ks][1], qf[ks][2], qf[ks][3],
                            kr[q], kr[q + 4]);
                }
            }

            // --- causal mask (diag band only) ---
            if (kv0 + 63 > rmin) {
                const int r0 = rmin + g, r1 = r0 + 8;
#pragma unroll
                for (int nt = 0; nt < 8; nt++) {
                    const int c0 = kv0 + nt * 8 + 2 * q, c1 = c0 + 1;
                    if (c0 > r0) sf[nt][0] = -1e30f;
                    if (c1 > r0) sf[nt][1] = -1e30f;
                    if (c0 > r1) sf[nt][2] = -1e30f;
                    if (c1 > r1) sf[nt][3] = -1e30f;
                }
            }

            // --- online softmax (exp2 domain), rows g / g+8 ---
            float mx0 = -1e30f, mx1 = -1e30f;
#pragma unroll
            for (int nt = 0; nt < 8; nt++) {
                mx0 = fmaxf(mx0, fmaxf(sf[nt][0], sf[nt][1]));
                mx1 = fmaxf(mx1, fmaxf(sf[nt][2], sf[nt][3]));
            }
            mx0 = fmaxf(mx0, __shfl_xor_sync(0xffffffffu, mx0, 1));
            mx0 = fmaxf(mx0, __shfl_xor_sync(0xffffffffu, mx0, 2));
            mx1 = fmaxf(mx1, __shfl_xor_sync(0xffffffffu, mx1, 1));
            mx1 = fmaxf(mx1, __shfl_xor_sync(0xffffffffu, mx1, 2));

            const float mn0 = fmaxf(m0, mx0), mn1 = fmaxf(m1, mx1);
            const float al0 = exp2f(m0 - mn0), al1 = exp2f(m1 - mn1);
            m0 = mn0; m1 = mn1;

            float rs0 = 0.0f, rs1 = 0.0f;
            __half2* pw0 = (__half2*)Ps + (w * 16 + g) * 36;
            __half2* pw1 = pw0 + 8 * 36;
#pragma unroll
            for (int nt = 0; nt < 8; nt++) {
                const float p00 = exp2f(sf[nt][0] - mn0);
                const float p01 = exp2f(sf[nt][1] - mn0);
                const float p10 = exp2f(sf[nt][2] - mn1);
                const float p11 = exp2f(sf[nt][3] - mn1);
                rs0 += p00 + p01;
                rs1 += p10 + p11;
                pw0[nt * 4 + q] = __floats2half2_rn(p00, p01);
                pw1[nt * 4 + q] = __floats2half2_rn(p10, p11);
            }
            rs0 += __shfl_xor_sync(0xffffffffu, rs0, 1);
            rs0 += __shfl_xor_sync(0xffffffffu, rs0, 2);
            rs1 += __shfl_xor_sync(0xffffffffu, rs1, 1);
            rs1 += __shfl_xor_sync(0xffffffffu, rs1, 2);
            l0 = l0 * al0 + rs0;
            l1 = l1 * al1 + rs1;

#pragma unroll
            for (int nt = 0; nt < 8; nt++) {
                acc[nt][0] *= al0; acc[nt][1] *= al0;
                acc[nt][2] *= al1; acc[nt][3] *= al1;
            }
            __syncwarp();   // P rows are warp-private

            // --- O += P @ V  (V transposed in smem: [d][kv]) ---
            const uint32_t* pa0 = (const uint32_t*)Ps + (w * 16 + g) * 36;
            const uint32_t* pa1 = pa0 + 8 * 36;
#pragma unroll
            for (int ks = 0; ks < 4; ks++) {
                const uint32_t a0 = pa0[ks * 8 + q];
                const uint32_t a1 = pa1[ks * 8 + q];
                const uint32_t a2 = pa0[ks * 8 + q + 4];
                const uint32_t a3 = pa1[ks * 8 + q + 4];
#pragma unroll
                for (int nt = 0; nt < 8; nt++) {
                    const uint32_t* vr = Vs32 + (nt * 8 + g) * 36 + ks * 8;
                    mma_f16(acc[nt][0], acc[nt][1], acc[nt][2], acc[nt][3],
                            a0, a1, a2, a3, vr[q], vr[q + 4]);
                }
            }
        }

        CP_WAIT0();        // next tile's data landed
        __syncthreads();   // stage reuse barrier (1 per tile)
    }

    // --- epilogue (half out for the Wo GEMM) ---
    const float inv0 = 1.0f / l0, inv1 = 1.0f / l1;
    const int r0 = q0 + w * 16 + g;
#pragma unroll
    for (int nt = 0; nt < 8; nt++) {
        const int col = nt * 8 + 2 * q;
        *(__half2*)(O + baseh + (size_t)r0 * DMODEL + col) =
            __floats2half2_rn(acc[nt][0] * inv0, acc[nt][1] * inv0);
        *(__half2*)(O + baseh + (size_t)(r0 + 8) * DMODEL + col) =
            __floats2half2_rn(acc[nt][2] * inv1, acc[nt][3] * inv1);
    }
}

// ---------------------------------------------------------------------------
// Launch
// ---------------------------------------------------------------------------
extern "C" void kernel_launch(void* const* d_in, const int* in_sizes, int n_in,
                              void* d_out, int out_size)
{
    const float* x  = (const float*)d_in[0];
    const float* Wq = (const float*)d_in[1];
    const float* Wk = (const float*)d_in[2];
    const float* Wv = (const float*)d_in[3];
    const float* Wo = (const float*)d_in[4];
    float* out = (float*)d_out;

    __half *xh, *wh, *qb, *kb, *vb, *ab;
    cudaGetSymbolAddress((void**)&xh, g_xh);
    cudaGetSymbolAddress((void**)&wh, g_wh);
    cudaGetSymbolAddress((void**)&qb, g_q);
    cudaGetSymbolAddress((void**)&kb, g_k);
    cudaGetSymbolAddress((void**)&vb, g_v);
    cudaGetSymbolAddress((void**)&ab, g_a);

    cudaFuncSetAttribute(gemm_qkv,
                         cudaFuncAttributeMaxDynamicSharedMemorySize, GEMM_SMEM);
    cudaFuncSetAttribute(gemm_out,
                         cudaFuncAttributeMaxDynamicSharedMemorySize, GEMM_SMEM);
    cudaFuncSetAttribute(flash_attn_f16,
                         cudaFuncAttributeMaxDynamicSharedMemorySize, FA_SMEM);

    // --- prepass: fp32 -> fp16 for x and all weights ---
    f2h<<<MROWS * DMODEL / 2048, 256>>>(x, xh, MROWS * DMODEL);
    f2h4<<<dim3(DMODEL * DMODEL / 2048, 4), 256>>>(Wq, Wk, Wv, Wo, wh);

    // softmax scale folds 1/sqrt(dk) and log2(e) (flash runs in exp2 domain)
    const float qscale = 0.125f * 1.4426950408889634f;

    // --- fused QKV projections (grid.z = 3) ---
    gemm_qkv<<<dim3(DMODEL / 128, MROWS / 128, 3), 256, GEMM_SMEM>>>(
        xh, wh, qb, kb, vb, qscale);

    flash_attn_f16<<<dim3(SEQ / 128, NHEAD, BSZ), 256, FA_SMEM>>>(qb, kb, vb, ab);

    gemm_out<<<dim3(DMODEL / 128, MROWS / 128), 256, GEMM_SMEM>>>(
        ab, wh + (size_t)3 * DMODEL * DMODEL, out);
}

// round 12
// speedup vs baseline: 1.0756x; 1.0756x over previous
#include <cuda_runtime.h>
#include <cuda_fp16.h>
#include <cstdint>

#define BSZ    2
#define SEQ    2048
#define DMODEL 1024
#define NHEAD  16
#define DKH    64
#define MROWS  (BSZ * SEQ)   // 4096

// Scratch (allocation-free rule: __device__ globals). All fp16.
__device__ __half g_xh[MROWS * DMODEL];          // x in half
__device__ __half g_wh[4 * DMODEL * DMODEL];     // Wq,Wk,Wv,Wo in half
__device__ __half g_q[MROWS * DMODEL];           // q (scaled)
__device__ __half g_k[MROWS * DMODEL];           // k
__device__ __half g_v[MROWS * DMODEL];           // vt[b][h][64][2048]
__device__ __half g_a[MROWS * DMODEL];           // attention output (half)

// ---------------------------------------------------------------------------
// helpers (sm_80+ features only — the build targets plain sm_103)
// ---------------------------------------------------------------------------
__device__ __forceinline__ void mma_f16(
    float& d0, float& d1, float& d2, float& d3,
    uint32_t a0, uint32_t a1, uint32_t a2, uint32_t a3,
    uint32_t b0, uint32_t b1)
{
    asm volatile(
        "mma.sync.aligned.m16n8k16.row.col.f32.f16.f16.f32 "
        "{%0,%1,%2,%3}, {%4,%5,%6,%7}, {%8,%9}, {%0,%1,%2,%3};"
        : "+f"(d0), "+f"(d1), "+f"(d2), "+f"(d3)
        : "r"(a0), "r"(a1), "r"(a2), "r"(a3), "r"(b0), "r"(b1));
}

__device__ __forceinline__ void ldsm_x4(
    uint32_t& r0, uint32_t& r1, uint32_t& r2, uint32_t& r3, uint32_t addr)
{
    asm volatile("ldmatrix.sync.aligned.m8n8.x4.shared.b16 {%0,%1,%2,%3}, [%4];"
                 : "=r"(r0), "=r"(r1), "=r"(r2), "=r"(r3) : "r"(addr));
}

__device__ __forceinline__ uint32_t smem_u32(const void* p) {
    uint32_t a;
    asm("{ .reg .u64 t; cvta.to.shared.u64 t, %1; cvt.u32.u64 %0, t; }"
        : "=r"(a) : "l"(p));
    return a;
}

__device__ __forceinline__ uint32_t h2u(__half2 h) {
    return *reinterpret_cast<uint32_t*>(&h);
}

__device__ __forceinline__ void cp16(uint32_t dst, const void* src) {
    asm volatile("cp.async.ca.shared.global [%0], [%1], 16;"
                 :: "r"(dst), "l"(src) : "memory");
}
#define CP_COMMIT() asm volatile("cp.async.commit_group;" ::: "memory")
#define CP_WAIT0()  asm volatile("cp.async.wait_group 0;" ::: "memory")
#define CP_WAIT1()  asm volatile("cp.async.wait_group 1;" ::: "memory")

// ---------------------------------------------------------------------------
// Prepass: fp32 -> fp16 conversion (producer-side; enables cp.async loaders)
// ---------------------------------------------------------------------------
__global__ __launch_bounds__(256) void f2h(
    const float* __restrict__ s, __half* __restrict__ d, int n)
{
    const int i = (blockIdx.x * 256 + threadIdx.x) * 8;
    if (i < n) {
        float4 a = *(const float4*)(s + i);
        float4 b = *(const float4*)(s + i + 4);
        union { __half2 h[4]; uint4 u; } u;
        u.h[0] = __floats2half2_rn(a.x, a.y);
        u.h[1] = __floats2half2_rn(a.z, a.w);
        u.h[2] = __floats2half2_rn(b.x, b.y);
        u.h[3] = __floats2half2_rn(b.z, b.w);
        *(uint4*)(d + i) = u.u;
    }
}

__global__ __launch_bounds__(256) void f2h4(
    const float* __restrict__ w0, const float* __restrict__ w1,
    const float* __restrict__ w2, const float* __restrict__ w3,
    __half* __restrict__ d)
{
    const float* srcs[4] = {w0, w1, w2, w3};
    const float* s = srcs[blockIdx.y];
    __half* dd = d + (size_t)blockIdx.y * DMODEL * DMODEL;
    const int i = (blockIdx.x * 256 + threadIdx.x) * 8;
    float4 a = *(const float4*)(s + i);
    float4 b = *(const float4*)(s + i + 4);
    union { __half2 h[4]; uint4 u; } u;
    u.h[0] = __floats2half2_rn(a.x, a.y);
    u.h[1] = __floats2half2_rn(a.z, a.w);
    u.h[2] = __floats2half2_rn(b.x, b.y);
    u.h[3] = __floats2half2_rn(b.z, b.w);
    *(uint4*)(dd + i) = u.u;
}

// ---------------------------------------------------------------------------
// fp16 GEMM NT body: C[m,n] = sum_k A[m,k] * W[n,k]   (half in; fp32 accum)
// 128x128 tile, BK=32, 8 warps (4Mx2N), cp.async 3-stage ring, ldmatrix frags.
// (unchanged from round 11 — validated)
// ---------------------------------------------------------------------------
#define GEMM_SMEM (3 * 16384)   // 49152 B

__device__ __forceinline__ void gemm_body(
    const __half* __restrict__ A, const __half* __restrict__ W,
    void* __restrict__ Cv, float oscale, int mode, char* smg)
{
    const int tid  = threadIdx.x;
    const int wid  = tid >> 5;
    const int lane = tid & 31;
    const int wm   = wid & 3;
    const int wn   = wid >> 2;
    const int m0 = blockIdx.y * 128;
    const int n0 = blockIdx.x * 128;
    const uint32_t smb = smem_u32(smg);

    const int lr  = tid >> 1;
    const int lc2 = (tid & 1) * 2;
    const __half* Ag = A + (size_t)(m0 + lr) * DMODEL + lc2 * 8;
    const __half* Wg = W + (size_t)(n0 + lr) * DMODEL + lc2 * 8;
    const uint32_t sA0 = lc2 * 2048 + lr * 16;
    const uint32_t sA1 = (lc2 + 1) * 2048 + lr * 16;

    float acc[2][8][4];
#pragma unroll
    for (int i = 0; i < 2; i++)
#pragma unroll
        for (int j = 0; j < 8; j++)
#pragma unroll
            for (int r = 0; r < 4; r++) acc[i][j][r] = 0.0f;

    const int NCH = DMODEL / 32;   // 32

#pragma unroll
    for (int s = 0; s < 2; s++) {
        const uint32_t st = smb + s * 16384;
        const int k0 = s * 32;
        cp16(st + sA0,        Ag + k0);
        cp16(st + sA1,        Ag + k0 + 8);
        cp16(st + 8192 + sA0, Wg + k0);
        cp16(st + 8192 + sA1, Wg + k0 + 8);
        CP_COMMIT();
    }

    for (int s = 0; s < NCH; s++) {
        if (s == NCH - 1) { CP_WAIT0(); } else { CP_WAIT1(); }
        __syncthreads();

        if (s + 2 < NCH) {
            const uint32_t st = smb + ((s + 2) % 3) * 16384;
            const int k0 = (s + 2) * 32;
            cp16(st + sA0,        Ag + k0);
            cp16(st + sA1,        Ag + k0 + 8);
            cp16(st + 8192 + sA0, Wg + k0);
            cp16(st + 8192 + sA1, Wg + k0 + 8);
            CP_COMMIT();
        }

        const uint32_t st = smb + (s % 3) * 16384;
#pragma unroll
        for (int ks = 0; ks < 2; ks++) {
            uint32_t af[2][4];
            uint32_t bf[8][2];
#pragma unroll
            for (int mt = 0; mt < 2; mt++) {
                const uint32_t addr = st + (2 * ks + (lane >> 4)) * 2048
                                    + (wm * 32 + mt * 16 + (lane & 15)) * 16;
                ldsm_x4(af[mt][0], af[mt][1], af[mt][2], af[mt][3], addr);
            }
#pragma unroll
            for (int p = 0; p < 4; p++) {
                const uint32_t addr = st + 8192 + (2 * ks + ((lane >> 3) & 1)) * 2048
                                    + (wn * 64 + p * 16 + ((lane >> 4) << 3) + (lane & 7)) * 16;
                ldsm_x4(bf[2 * p][0], bf[2 * p][1], bf[2 * p + 1][0], bf[2 * p + 1][1], addr);
            }
#pragma unroll
            for (int mt = 0; mt < 2; mt++)
#pragma unroll
                for (int nt = 0; nt < 8; nt++)
                    mma_f16(acc[mt][nt][0], acc[mt][nt][1],
                            acc[mt][nt][2], acc[mt][nt][3],
                            af[mt][0], af[mt][1], af[mt][2], af[mt][3],
                            bf[nt][0], bf[nt][1]);
        }
    }

    const int g = lane >> 2, q = lane & 3;
#pragma unroll
    for (int mt = 0; mt < 2; mt++) {
        const int mrow = m0 + wm * 32 + mt * 16 + g;
#pragma unroll
        for (int nt = 0; nt < 8; nt++) {
            const int ncol = n0 + wn * 64 + nt * 8 + 2 * q;
            if (mode == 0) {
                float* C = (float*)Cv;
                *(float2*)(C + (size_t)mrow * DMODEL + ncol) =
                    make_float2(acc[mt][nt][0], acc[mt][nt][1]);
                *(float2*)(C + (size_t)(mrow + 8) * DMODEL + ncol) =
                    make_float2(acc[mt][nt][2], acc[mt][nt][3]);
            } else if (mode == 1) {
                __half2* C = (__half2*)Cv;
                C[((size_t)mrow * DMODEL + ncol) >> 1] =
                    __floats2half2_rn(acc[mt][nt][0] * oscale, acc[mt][nt][1] * oscale);
                C[((size_t)(mrow + 8) * DMODEL + ncol) >> 1] =
                    __floats2half2_rn(acc[mt][nt][2] * oscale, acc[mt][nt][3] * oscale);
            } else {
                // vt[((b*NHEAD + h)*64 + d) * SEQ + s]
                __half* C = (__half*)Cv;
                const int h = ncol >> 6, d = ncol & 63;
                const size_t hb = ((size_t)((mrow >> 11) * NHEAD + h) * 64);
                const int s0 = mrow & 2047;
                C[(hb + d)     * SEQ + s0]     = __float2half_rn(acc[mt][nt][0]);
                C[(hb + d + 1) * SEQ + s0]     = __float2half_rn(acc[mt][nt][1]);
                C[(hb + d)     * SEQ + s0 + 8] = __float2half_rn(acc[mt][nt][2]);
                C[(hb + d + 1) * SEQ + s0 + 8] = __float2half_rn(acc[mt][nt][3]);
            }
        }
    }
}

__global__ __launch_bounds__(256, 2) void gemm_qkv(
    const __half* __restrict__ xh, const __half* __restrict__ wh,
    __half* __restrict__ qb, __half* __restrict__ kb, __half* __restrict__ vb,
    float qscale)
{
    extern __shared__ char smg[];
    const int z = blockIdx.z;
    const __half* W = wh + (size_t)z * DMODEL * DMODEL;
    void* C   = (z == 0) ? (void*)qb : (z == 1) ? (void*)kb : (void*)vb;
    const float sc = (z == 0) ? qscale : 1.0f;
    const int mode = (z == 2) ? 2 : 1;
    gemm_body(xh, W, C, sc, mode, smg);
}

__global__ __launch_bounds__(256, 2) void gemm_out(
    const __half* __restrict__ A, const __half* __restrict__ W,
    float* __restrict__ C)
{
    extern __shared__ char smg[];
    gemm_body(A, W, C, 1.0f, 0, smg);
}

// ---------------------------------------------------------------------------
// fp16 tensor-core flash attention (causal). BQ=128 (8 warps x m16), BKV=64.
// Q/K half [B*S][D] (head slices); V half transposed vt[b][h][64][2048].
// 2-stage cp.async ring; ONE barrier per tile; reversed qb (LPT).
// P kept entirely in registers: S C-fragments ARE PV A-fragments (m16n8k16
// thread-local identity). K/V fragments via ldmatrix.x4 (144B row stride ->
// rows 4 banks apart -> conflict-free).
// ---------------------------------------------------------------------------
#define FH_LD        72
#define FH_LDB       (FH_LD * 2)              // 144 bytes per row
#define FH_PS_HALVES (128 * FH_LD)            // 9216 (Q staging)
#define FH_STG_HALVES (2 * 64 * FH_LD)        // 9216 (K + V)
#define FA_SMEM ((FH_PS_HALVES + 2 * FH_STG_HALVES) * 2)   // 55296 B

__global__ __launch_bounds__(256, 2) void flash_attn_f16(
    const __half* __restrict__ Q, const __half* __restrict__ K,
    const __half* __restrict__ Vt, __half* __restrict__ O)
{
    extern __shared__ __half sh[];
    __half* Ps = sh;                          // 128 x 72 (Q staging only)

    const int tid  = threadIdx.x;
    const int w    = tid >> 5;
    const int lane = tid & 31;
    const int g    = lane >> 2;
    const int q    = lane & 3;
    const int qb = gridDim.x - 1 - blockIdx.x;   // reversed: longest first
    const int h  = blockIdx.y, b = blockIdx.z;
    const int q0 = qb * 128;
    const size_t baseh = (size_t)b * SEQ * DMODEL + (size_t)h * DKH;   // half idx
    const size_t vbase = ((size_t)(b * NHEAD + h)) * 64 * SEQ;         // vt half idx

    const uint32_t smb = smem_u32(sh);

    // ldmatrix per-lane row/k offsets (same pattern as the validated GEMM)
    const uint32_t lm_row = ((lane >> 4) << 3) + (lane & 7);   // row within 16-row group
    const uint32_t lm_koff = 8 * ((lane >> 3) & 1) * 2;        // byte offset of k-half

    const int ntiles = 2 * qb + 2;

    // --- prologue: async-stage Q (128 rows x 128B) and KV tile 0 ---
    for (int i = tid; i < 128 * 8; i += 256) {
        const int r = i >> 3, c = (i & 7) * 8;             // halves
        cp16(smb + (r * FH_LD + c) * 2, Q + baseh + (size_t)(q0 + r) * DMODEL + c);
    }
    {
        const int lrk = tid >> 3, lck = (tid & 7) * 8;     // 32 rows x 8-half chunks
        const uint32_t kb0 = smb + FH_PS_HALVES * 2;
        const uint32_t vb0 = kb0 + 64 * FH_LD * 2;
#pragma unroll
        for (int j = 0; j < 2; j++) {
            const int r = lrk + 32 * j;
            cp16(kb0 + (r * FH_LD + lck) * 2, K + baseh + (size_t)r * DMODEL + lck);
            cp16(vb0 + (r * FH_LD + lck) * 2, Vt + vbase + (size_t)r * SEQ + lck);
        }
    }
    CP_COMMIT();
    CP_WAIT0();
    __syncthreads();

    // --- lift Q to register fragments: qf[ks][4], ks over dk (4 x k16) ---
    uint32_t qf[4][4];
    {
        const uint32_t* r0p = (const uint32_t*)Ps + (w * 16 + g) * 36;
        const uint32_t* r1p = r0p + 8 * 36;
#pragma unroll
        for (int ks = 0; ks < 4; ks++) {
            qf[ks][0] = r0p[ks * 8 + q];
            qf[ks][1] = r1p[ks * 8 + q];
            qf[ks][2] = r0p[ks * 8 + q + 4];
            qf[ks][3] = r1p[ks * 8 + q + 4];
        }
    }

    float m0 = -1e30f, m1 = -1e30f, l0 = 0.0f, l1 = 0.0f;
    float acc[8][4];
#pragma unroll
    for (int nt = 0; nt < 8; nt++)
#pragma unroll
        for (int r = 0; r < 4; r++) acc[nt][r] = 0.0f;

    const int rmin = q0 + w * 16;
    const int rmax = rmin + 15;

    for (int kb = 0; kb < ntiles; kb++) {
        const int kv0 = kb * 64;

        // --- issue cp.async for next tile into the other stage ---
        if (kb + 1 < ntiles) {
            const int lrk = tid >> 3, lck = (tid & 7) * 8;
            const uint32_t kbn = smb + (FH_PS_HALVES + ((kb + 1) & 1) * FH_STG_HALVES) * 2;
            const uint32_t vbn = kbn + 64 * FH_LD * 2;
#pragma unroll
            for (int j = 0; j < 2; j++) {
                const int r = lrk + 32 * j;
                cp16(kbn + (r * FH_LD + lck) * 2,
                     K + baseh + (size_t)(kv0 + 64 + r) * DMODEL + lck);
                cp16(vbn + (r * FH_LD + lck) * 2,
                     Vt + vbase + (size_t)r * SEQ + kv0 + 64 + lck);
            }
            CP_COMMIT();
        }

        const uint32_t ksb = smb + (FH_PS_HALVES + (kb & 1) * FH_STG_HALVES) * 2;
        const uint32_t vsb = ksb + 64 * FH_LD * 2;

        if (kv0 <= rmax) {
            // --- S = Q @ K^T (K B-fragments via ldmatrix.x4) ---
            float sf[8][4];
#pragma unroll
            for (int nt = 0; nt < 8; nt++)
#pragma unroll
                for (int r = 0; r < 4; r++) sf[nt][r] = 0.0f;

#pragma unroll
            for (int ks = 0; ks < 4; ks++) {
                uint32_t bf[8][2];
#pragma unroll
                for (int p = 0; p < 4; p++) {
                    const uint32_t addr = ksb + (p * 16 + lm_row) * FH_LDB
                                        + ks * 32 + lm_koff;
                    ldsm_x4(bf[2 * p][0], bf[2 * p][1],
                            bf[2 * p + 1][0], bf[2 * p + 1][1], addr);
                }
#pragma unroll
                for (int nt = 0; nt < 8; nt++)
                    mma_f16(sf[nt][0], sf[nt][1], sf[nt][2], sf[nt][3],
                            qf[ks][0], qf[ks][1], qf[ks][2], qf[ks][3],
                            bf[nt][0], bf[nt][1]);
            }

            // --- causal mask (diag band only) ---
            if (kv0 + 63 > rmin) {
                const int r0 = rmin + g, r1 = r0 + 8;
#pragma unroll
                for (int nt = 0; nt < 8; nt++) {
                    const int c0 = kv0 + nt * 8 + 2 * q, c1 = c0 + 1;
                    if (c0 > r0) sf[nt][0] = -1e30f;
                    if (c1 > r0) sf[nt][1] = -1e30f;
                    if (c0 > r1) sf[nt][2] = -1e30f;
                    if (c1 > r1) sf[nt][3] = -1e30f;
                }
            }

            // --- online softmax (exp2 domain), rows g / g+8; P -> registers ---
            float mx0 = -1e30f, mx1 = -1e30f;
#pragma unroll
            for (int nt = 0; nt < 8; nt++) {
                mx0 = fmaxf(mx0, fmaxf(sf[nt][0], sf[nt][1]));
                mx1 = fmaxf(mx1, fmaxf(sf[nt][2], sf[nt][3]));
            }
            mx0 = fmaxf(mx0, __shfl_xor_sync(0xffffffffu, mx0, 1));
            mx0 = fmaxf(mx0, __shfl_xor_sync(0xffffffffu, mx0, 2));
            mx1 = fmaxf(mx1, __shfl_xor_sync(0xffffffffu, mx1, 1));
            mx1 = fmaxf(mx1, __shfl_xor_sync(0xffffffffu, mx1, 2));

            const float mn0 = fmaxf(m0, mx0), mn1 = fmaxf(m1, mx1);
            const float al0 = exp2f(m0 - mn0), al1 = exp2f(m1 - mn1);
            m0 = mn0; m1 = mn1;

            float rs0 = 0.0f, rs1 = 0.0f;
            uint32_t pf[8][2];   // P as PV A-fragments (thread-local identity)
#pragma unroll
            for (int nt = 0; nt < 8; nt++) {
                const float p00 = exp2f(sf[nt][0] - mn0);
                const float p01 = exp2f(sf[nt][1] - mn0);
                const float p10 = exp2f(sf[nt][2] - mn1);
                const float p11 = exp2f(sf[nt][3] - mn1);
                rs0 += p00 + p01;
                rs1 += p10 + p11;
                pf[nt][0] = h2u(__floats2half2_rn(p00, p01));
                pf[nt][1] = h2u(__floats2half2_rn(p10, p11));
            }
            rs0 += __shfl_xor_sync(0xffffffffu, rs0, 1);
            rs0 += __shfl_xor_sync(0xffffffffu, rs0, 2);
            rs1 += __shfl_xor_sync(0xffffffffu, rs1, 1);
            rs1 += __shfl_xor_sync(0xffffffffu, rs1, 2);
            l0 = l0 * al0 + rs0;
            l1 = l1 * al1 + rs1;

#pragma unroll
            for (int nt = 0; nt < 8; nt++) {
                acc[nt][0] *= al0; acc[nt][1] *= al0;
                acc[nt][2] *= al1; acc[nt][3] *= al1;
            }

            // --- O += P @ V (V B-fragments via ldmatrix.x4; P from registers) ---
#pragma unroll
            for (int ks = 0; ks < 4; ks++) {
                uint32_t bf[8][2];
#pragma unroll
                for (int p = 0; p < 4; p++) {
                    const uint32_t addr = vsb + (p * 16 + lm_row) * FH_LDB
                                        + ks * 32 + lm_koff;
                    ldsm_x4(bf[2 * p][0], bf[2 * p][1],
                            bf[2 * p + 1][0], bf[2 * p + 1][1], addr);
                }
                const uint32_t a0 = pf[2 * ks][0];
                const uint32_t a1 = pf[2 * ks][1];
                const uint32_t a2 = pf[2 * ks + 1][0];
                const uint32_t a3 = pf[2 * ks + 1][1];
#pragma unroll
                for (int nt = 0; nt < 8; nt++)
                    mma_f16(acc[nt][0], acc[nt][1], acc[nt][2], acc[nt][3],
                            a0, a1, a2, a3, bf[nt][0], bf[nt][1]);
            }
        }

        CP_WAIT0();        // next tile's data landed
        __syncthreads();   // stage reuse barrier (1 per tile)
    }

    // --- epilogue (half out for the Wo GEMM) ---
    const float inv0 = 1.0f / l0, inv1 = 1.0f / l1;
    const int r0 = q0 + w * 16 + g;
#pragma unroll
    for (int nt = 0; nt < 8; nt++) {
        const int col = nt * 8 + 2 * q;
        *(__half2*)(O + baseh + (size_t)r0 * DMODEL + col) =
            __floats2half2_rn(acc[nt][0] * inv0, acc[nt][1] * inv0);
        *(__half2*)(O + baseh + (size_t)(r0 + 8) * DMODEL + col) =
            __floats2half2_rn(acc[nt][2] * inv1, acc[nt][3] * inv1);
    }
}

// ---------------------------------------------------------------------------
// Launch
// ---------------------------------------------------------------------------
extern "C" void kernel_launch(void* const* d_in, const int* in_sizes, int n_in,
                              void* d_out, int out_size)
{
    const float* x  = (const float*)d_in[0];
    const float* Wq = (const float*)d_in[1];
    const float* Wk = (const float*)d_in[2];
    const float* Wv = (const float*)d_in[3];
    const float* Wo = (const float*)d_in[4];
    float* out = (float*)d_out;

    __half *xh, *wh, *qb, *kb, *vb, *ab;
    cudaGetSymbolAddress((void**)&xh, g_xh);
    cudaGetSymbolAddress((void**)&wh, g_wh);
    cudaGetSymbolAddress((void**)&qb, g_q);
    cudaGetSymbolAddress((void**)&kb, g_k);
    cudaGetSymbolAddress((void**)&vb, g_v);
    cudaGetSymbolAddress((void**)&ab, g_a);

    cudaFuncSetAttribute(gemm_qkv,
                         cudaFuncAttributeMaxDynamicSharedMemorySize, GEMM_SMEM);
    cudaFuncSetAttribute(gemm_out,
                         cudaFuncAttributeMaxDynamicSharedMemorySize, GEMM_SMEM);
    cudaFuncSetAttribute(flash_attn_f16,
                         cudaFuncAttributeMaxDynamicSharedMemorySize, FA_SMEM);

    // --- prepass: fp32 -> fp16 for x and all weights ---
    f2h<<<MROWS * DMODEL / 2048, 256>>>(x, xh, MROWS * DMODEL);
    f2h4<<<dim3(DMODEL * DMODEL / 2048, 4), 256>>>(Wq, Wk, Wv, Wo, wh);

    // softmax scale folds 1/sqrt(dk) and log2(e) (flash runs in exp2 domain)
    const float qscale = 0.125f * 1.4426950408889634f;

    // --- fused QKV projections (grid.z = 3) ---
    gemm_qkv<<<dim3(DMODEL / 128, MROWS / 128, 3), 256, GEMM_SMEM>>>(
        xh, wh, qb, kb, vb, qscale);

    flash_attn_f16<<<dim3(SEQ / 128, NHEAD, BSZ), 256, FA_SMEM>>>(qb, kb, vb, ab);

    gemm_out<<<dim3(DMODEL / 128, MROWS / 128), 256, GEMM_SMEM>>>(
        ab, wh + (size_t)3 * DMODEL * DMODEL, out);
}

// round 13
// speedup vs baseline: 1.0771x; 1.0015x over previous
#include <cuda_runtime.h>
#include <cuda_fp16.h>
#include <cstdint>

#define BSZ    2
#define SEQ    2048
#define DMODEL 1024
#define NHEAD  16
#define DKH    64
#define MROWS  (BSZ * SEQ)   // 4096

// Scratch (allocation-free rule: __device__ globals). All fp16.
__device__ __half g_xh[MROWS * DMODEL];          // x in half
__device__ __half g_wh[4 * DMODEL * DMODEL];     // Wq,Wk,Wv,Wo in half
__device__ __half g_q[MROWS * DMODEL];           // q (scaled)
__device__ __half g_k[MROWS * DMODEL];           // k
__device__ __half g_v[MROWS * DMODEL];           // vt[b][h][64][2048]
__device__ __half g_a[MROWS * DMODEL];           // attention output (half)

// ---------------------------------------------------------------------------
// helpers (sm_80+ features only — the build targets plain sm_103)
// ---------------------------------------------------------------------------
__device__ __forceinline__ void mma_f16(
    float& d0, float& d1, float& d2, float& d3,
    uint32_t a0, uint32_t a1, uint32_t a2, uint32_t a3,
    uint32_t b0, uint32_t b1)
{
    asm volatile(
        "mma.sync.aligned.m16n8k16.row.col.f32.f16.f16.f32 "
        "{%0,%1,%2,%3}, {%4,%5,%6,%7}, {%8,%9}, {%0,%1,%2,%3};"
        : "+f"(d0), "+f"(d1), "+f"(d2), "+f"(d3)
        : "r"(a0), "r"(a1), "r"(a2), "r"(a3), "r"(b0), "r"(b1));
}

__device__ __forceinline__ void ldsm_x4(
    uint32_t& r0, uint32_t& r1, uint32_t& r2, uint32_t& r3, uint32_t addr)
{
    asm volatile("ldmatrix.sync.aligned.m8n8.x4.shared.b16 {%0,%1,%2,%3}, [%4];"
                 : "=r"(r0), "=r"(r1), "=r"(r2), "=r"(r3) : "r"(addr));
}

__device__ __forceinline__ uint32_t smem_u32(const void* p) {
    uint32_t a;
    asm("{ .reg .u64 t; cvta.to.shared.u64 t, %1; cvt.u32.u64 %0, t; }"
        : "=r"(a) : "l"(p));
    return a;
}

__device__ __forceinline__ uint32_t h2u(__half2 h) {
    return *reinterpret_cast<uint32_t*>(&h);
}

// packed half2 exp2 (sm_75+): one MUFU op per pair
__device__ __forceinline__ uint32_t ex2_h2(uint32_t x) {
    uint32_t r;
    asm("ex2.approx.f16x2 %0, %1;" : "=r"(r) : "r"(x));
    return r;
}

__device__ __forceinline__ void cp16(uint32_t dst, const void* src) {
    asm volatile("cp.async.ca.shared.global [%0], [%1], 16;"
                 :: "r"(dst), "l"(src) : "memory");
}
#define CP_COMMIT() asm volatile("cp.async.commit_group;" ::: "memory")
#define CP_WAIT0()  asm volatile("cp.async.wait_group 0;" ::: "memory")

// ---------------------------------------------------------------------------
// Prepass: fp32 -> fp16 conversion (producer-side; enables cp.async loaders)
// ---------------------------------------------------------------------------
__global__ __launch_bounds__(256) void f2h(
    const float* __restrict__ s, __half* __restrict__ d, int n)
{
    const int i = (blockIdx.x * 256 + threadIdx.x) * 8;
    if (i < n) {
        float4 a = *(const float4*)(s + i);
        float4 b = *(const float4*)(s + i + 4);
        union { __half2 h[4]; uint4 u; } u;
        u.h[0] = __floats2half2_rn(a.x, a.y);
        u.h[1] = __floats2half2_rn(a.z, a.w);
        u.h[2] = __floats2half2_rn(b.x, b.y);
        u.h[3] = __floats2half2_rn(b.z, b.w);
        *(uint4*)(d + i) = u.u;
    }
}

__global__ __launch_bounds__(256) void f2h4(
    const float* __restrict__ w0, const float* __restrict__ w1,
    const float* __restrict__ w2, const float* __restrict__ w3,
    __half* __restrict__ d)
{
    const float* srcs[4] = {w0, w1, w2, w3};
    const float* s = srcs[blockIdx.y];
    __half* dd = d + (size_t)blockIdx.y * DMODEL * DMODEL;
    const int i = (blockIdx.x * 256 + threadIdx.x) * 8;
    float4 a = *(const float4*)(s + i);
    float4 b = *(const float4*)(s + i + 4);
    union { __half2 h[4]; uint4 u; } u;
    u.h[0] = __floats2half2_rn(a.x, a.y);
    u.h[1] = __floats2half2_rn(a.z, a.w);
    u.h[2] = __floats2half2_rn(b.x, b.y);
    u.h[3] = __floats2half2_rn(b.z, b.w);
    *(uint4*)(dd + i) = u.u;
}

// ---------------------------------------------------------------------------
// fp16 GEMM NT body: C[m,n] = sum_k A[m,k] * W[n,k]   (half in; fp32 accum)
// 128x128 tile, BK=64, 8 warps (4Mx2N), cp.async 2-stage ring, ldmatrix frags.
// Smem per stage 32KB: A chunk-major [8][128][16B] at 0; B same at 16384.
// ---------------------------------------------------------------------------
#define GEMM_SMEM (2 * 32768)   // 65536 B

__device__ __forceinline__ void gemm_body(
    const __half* __restrict__ A, const __half* __restrict__ W,
    void* __restrict__ Cv, float oscale, int mode, char* smg)
{
    const int tid  = threadIdx.x;
    const int lane = tid & 31;
    const int wm   = (tid >> 5) & 3;
    const int wn   = tid >> 7;
    const int m0 = blockIdx.y * 128;
    const int n0 = blockIdx.x * 128;
    const uint32_t smb = smem_u32(smg);

    // loader: row = tid>>1 (0..127), 4 chunk-slots per thread
    const int lr  = tid >> 1;
    const int lc4 = (tid & 1) * 4;
    const __half* Ag = A + (size_t)(m0 + lr) * DMODEL + lc4 * 8;
    const __half* Wg = W + (size_t)(n0 + lr) * DMODEL + lc4 * 8;
    const uint32_t sBase = lc4 * 2048 + lr * 16;

    float acc[2][8][4];
#pragma unroll
    for (int i = 0; i < 2; i++)
#pragma unroll
        for (int j = 0; j < 8; j++)
#pragma unroll
            for (int r = 0; r < 4; r++) acc[i][j][r] = 0.0f;

    const int NCH = DMODEL / 64;   // 16

    // prologue: chunk 0 into stage 0
#pragma unroll
    for (int j = 0; j < 4; j++) {
        cp16(smb + sBase + j * 2048,         Ag + j * 8);
        cp16(smb + 16384 + sBase + j * 2048, Wg + j * 8);
    }
    CP_COMMIT();

    for (int s = 0; s < NCH; s++) {
        CP_WAIT0();
        __syncthreads();

        if (s + 1 < NCH) {
            const uint32_t st = smb + ((s + 1) & 1) * 32768;
            const int k0 = (s + 1) * 64;
#pragma unroll
            for (int j = 0; j < 4; j++) {
                cp16(st + sBase + j * 2048,         Ag + k0 + j * 8);
                cp16(st + 16384 + sBase + j * 2048, Wg + k0 + j * 8);
            }
            CP_COMMIT();
        }

        const uint32_t st = smb + (s & 1) * 32768;
#pragma unroll
        for (int ks = 0; ks < 4; ks++) {
            uint32_t af[2][4];
            uint32_t bf[8][2];
#pragma unroll
            for (int mt = 0; mt < 2; mt++) {
                const uint32_t addr = st + (2 * ks + (lane >> 4)) * 2048
                                    + (wm * 32 + mt * 16 + (lane & 15)) * 16;
                ldsm_x4(af[mt][0], af[mt][1], af[mt][2], af[mt][3], addr);
            }
#pragma unroll
            for (int p = 0; p < 4; p++) {
                const uint32_t addr = st + 16384 + (2 * ks + ((lane >> 3) & 1)) * 2048
                                    + (wn * 64 + p * 16 + ((lane >> 4) << 3) + (lane & 7)) * 16;
                ldsm_x4(bf[2 * p][0], bf[2 * p][1], bf[2 * p + 1][0], bf[2 * p + 1][1], addr);
            }
#pragma unroll
            for (int mt = 0; mt < 2; mt++)
#pragma unroll
                for (int nt = 0; nt < 8; nt++)
                    mma_f16(acc[mt][nt][0], acc[mt][nt][1],
                            acc[mt][nt][2], acc[mt][nt][3],
                            af[mt][0], af[mt][1], af[mt][2], af[mt][3],
                            bf[nt][0], bf[nt][1]);
        }
    }

    const int g = lane >> 2, q = lane & 3;
#pragma unroll
    for (int mt = 0; mt < 2; mt++) {
        const int mrow = m0 + wm * 32 + mt * 16 + g;
#pragma unroll
        for (int nt = 0; nt < 8; nt++) {
            const int ncol = n0 + wn * 64 + nt * 8 + 2 * q;
            if (mode == 0) {
                float* C = (float*)Cv;
                *(float2*)(C + (size_t)mrow * DMODEL + ncol) =
                    make_float2(acc[mt][nt][0], acc[mt][nt][1]);
                *(float2*)(C + (size_t)(mrow + 8) * DMODEL + ncol) =
                    make_float2(acc[mt][nt][2], acc[mt][nt][3]);
            } else if (mode == 1) {
                __half2* C = (__half2*)Cv;
                C[((size_t)mrow * DMODEL + ncol) >> 1] =
                    __floats2half2_rn(acc[mt][nt][0] * oscale, acc[mt][nt][1] * oscale);
                C[((size_t)(mrow + 8) * DMODEL + ncol) >> 1] =
                    __floats2half2_rn(acc[mt][nt][2] * oscale, acc[mt][nt][3] * oscale);
            } else {
                // vt[((b*NHEAD + h)*64 + d) * SEQ + s]
                __half* C = (__half*)Cv;
                const int h = ncol >> 6, d = ncol & 63;
                const size_t hb = ((size_t)((mrow >> 11) * NHEAD + h) * 64);
                const int s0 = mrow & 2047;
                C[(hb + d)     * SEQ + s0]     = __float2half_rn(acc[mt][nt][0]);
                C[(hb + d + 1) * SEQ + s0]     = __float2half_rn(acc[mt][nt][1]);
                C[(hb + d)     * SEQ + s0 + 8] = __float2half_rn(acc[mt][nt][2]);
                C[(hb + d + 1) * SEQ + s0 + 8] = __float2half_rn(acc[mt][nt][3]);
            }
        }
    }
}

__global__ __launch_bounds__(256, 2) void gemm_qkv(
    const __half* __restrict__ xh, const __half* __restrict__ wh,
    __half* __restrict__ qb, __half* __restrict__ kb, __half* __restrict__ vb,
    float qscale)
{
    extern __shared__ char smg[];
    const int z = blockIdx.z;
    const __half* W = wh + (size_t)z * DMODEL * DMODEL;
    void* C   = (z == 0) ? (void*)qb : (z == 1) ? (void*)kb : (void*)vb;
    const float sc = (z == 0) ? qscale : 1.0f;
    const int mode = (z == 2) ? 2 : 1;
    gemm_body(xh, W, C, sc, mode, smg);
}

__global__ __launch_bounds__(256, 2) void gemm_out(
    const __half* __restrict__ A, const __half* __restrict__ W,
    float* __restrict__ C)
{
    extern __shared__ char smg[];
    gemm_body(A, W, C, 1.0f, 0, smg);
}

// ---------------------------------------------------------------------------
// fp16 tensor-core flash attention (causal). BQ=128 (8 warps x m16), BKV=64.
// P in registers (S C-frag == PV A-frag identity); K/V frags via ldmatrix.x4.
// Softmax: ex2.approx.f16x2 (halved MUFU); row-sum l via ones-column MMA
// (l is just another rescaled accumulator — no shfl reduction).
// ---------------------------------------------------------------------------
#define FH_LD        72
#define FH_LDB       (FH_LD * 2)              // 144 bytes per row
#define FH_PS_HALVES (128 * FH_LD)            // 9216 (Q staging)
#define FH_STG_HALVES (2 * 64 * FH_LD)        // 9216 (K + V)
#define FA_SMEM ((FH_PS_HALVES + 2 * FH_STG_HALVES) * 2)   // 55296 B
#define ONES_H2 0x3C003C00u                   // half2(1.0, 1.0)

__global__ __launch_bounds__(256, 2) void flash_attn_f16(
    const __half* __restrict__ Q, const __half* __restrict__ K,
    const __half* __restrict__ Vt, __half* __restrict__ O)
{
    extern __shared__ __half sh[];
    __half* Ps = sh;                          // 128 x 72 (Q staging only)

    const int tid  = threadIdx.x;
    const int w    = tid >> 5;
    const int lane = tid & 31;
    const int g    = lane >> 2;
    const int q    = lane & 3;
    const int qb = gridDim.x - 1 - blockIdx.x;   // reversed: longest first
    const int h  = blockIdx.y, b = blockIdx.z;
    const int q0 = qb * 128;
    const size_t baseh = (size_t)b * SEQ * DMODEL + (size_t)h * DKH;   // half idx
    const size_t vbase = ((size_t)(b * NHEAD + h)) * 64 * SEQ;         // vt half idx

    const uint32_t smb = smem_u32(sh);

    const uint32_t lm_row = ((lane >> 4) << 3) + (lane & 7);
    const uint32_t lm_koff = 8 * ((lane >> 3) & 1) * 2;

    const int ntiles = 2 * qb + 2;

    // --- prologue: async-stage Q (128 rows x 128B) and KV tile 0 ---
    for (int i = tid; i < 128 * 8; i += 256) {
        const int r = i >> 3, c = (i & 7) * 8;
        cp16(smb + (r * FH_LD + c) * 2, Q + baseh + (size_t)(q0 + r) * DMODEL + c);
    }
    {
        const int lrk = tid >> 3, lck = (tid & 7) * 8;
        const uint32_t kb0 = smb + FH_PS_HALVES * 2;
        const uint32_t vb0 = kb0 + 64 * FH_LD * 2;
#pragma unroll
        for (int j = 0; j < 2; j++) {
            const int r = lrk + 32 * j;
            cp16(kb0 + (r * FH_LD + lck) * 2, K + baseh + (size_t)r * DMODEL + lck);
            cp16(vb0 + (r * FH_LD + lck) * 2, Vt + vbase + (size_t)r * SEQ + lck);
        }
    }
    CP_COMMIT();
    CP_WAIT0();
    __syncthreads();

    // --- lift Q to register fragments: qf[ks][4], ks over dk (4 x k16) ---
    uint32_t qf[4][4];
    {
        const uint32_t* r0p = (const uint32_t*)Ps + (w * 16 + g) * 36;
        const uint32_t* r1p = r0p + 8 * 36;
#pragma unroll
        for (int ks = 0; ks < 4; ks++) {
            qf[ks][0] = r0p[ks * 8 + q];
            qf[ks][1] = r1p[ks * 8 + q];
            qf[ks][2] = r0p[ks * 8 + q + 4];
            qf[ks][3] = r1p[ks * 8 + q + 4];
        }
    }

    float m0 = -1e30f, m1 = -1e30f;
    float lacc[4] = {0.0f, 0.0f, 0.0f, 0.0f};   // row-sum accumulator (MMA-fed)
    float acc[8][4];
#pragma unroll
    for (int nt = 0; nt < 8; nt++)
#pragma unroll
        for (int r = 0; r < 4; r++) acc[nt][r] = 0.0f;

    const int rmin = q0 + w * 16;
    const int rmax = rmin + 15;

    for (int kb = 0; kb < ntiles; kb++) {
        const int kv0 = kb * 64;

        // --- issue cp.async for next tile into the other stage ---
        if (kb + 1 < ntiles) {
            const int lrk = tid >> 3, lck = (tid & 7) * 8;
            const uint32_t kbn = smb + (FH_PS_HALVES + ((kb + 1) & 1) * FH_STG_HALVES) * 2;
            const uint32_t vbn = kbn + 64 * FH_LD * 2;
#pragma unroll
            for (int j = 0; j < 2; j++) {
                const int r = lrk + 32 * j;
                cp16(kbn + (r * FH_LD + lck) * 2,
                     K + baseh + (size_t)(kv0 + 64 + r) * DMODEL + lck);
                cp16(vbn + (r * FH_LD + lck) * 2,
                     Vt + vbase + (size_t)r * SEQ + kv0 + 64 + lck);
            }
            CP_COMMIT();
        }

        const uint32_t ksb = smb + (FH_PS_HALVES + (kb & 1) * FH_STG_HALVES) * 2;
        const uint32_t vsb = ksb + 64 * FH_LD * 2;

        if (kv0 <= rmax) {
            // --- S = Q @ K^T ---
            float sf[8][4];
#pragma unroll
            for (int nt = 0; nt < 8; nt++)
#pragma unroll
                for (int r = 0; r < 4; r++) sf[nt][r] = 0.0f;

#pragma unroll
            for (int ks = 0; ks < 4; ks++) {
                uint32_t bf[8][2];
#pragma unroll
                for (int p = 0; p < 4; p++) {
                    const uint32_t addr = ksb + (p * 16 + lm_row) * FH_LDB
                                        + ks * 32 + lm_koff;
                    ldsm_x4(bf[2 * p][0], bf[2 * p][1],
                            bf[2 * p + 1][0], bf[2 * p + 1][1], addr);
                }
#pragma unroll
                for (int nt = 0; nt < 8; nt++)
                    mma_f16(sf[nt][0], sf[nt][1], sf[nt][2], sf[nt][3],
                            qf[ks][0], qf[ks][1], qf[ks][2], qf[ks][3],
                            bf[nt][0], bf[nt][1]);
            }

            // --- causal mask (diag band only) ---
            if (kv0 + 63 > rmin) {
                const int r0 = rmin + g, r1 = r0 + 8;
#pragma unroll
                for (int nt = 0; nt < 8; nt++) {
                    const int c0 = kv0 + nt * 8 + 2 * q, c1 = c0 + 1;
                    if (c0 > r0) sf[nt][0] = -1e30f;
                    if (c1 > r0) sf[nt][1] = -1e30f;
                    if (c0 > r1) sf[nt][2] = -1e30f;
                    if (c1 > r1) sf[nt][3] = -1e30f;
                }
            }

            // --- online softmax (exp2 domain), rows g / g+8 ---
            float mx0 = -1e30f, mx1 = -1e30f;
#pragma unroll
            for (int nt = 0; nt < 8; nt++) {
                mx0 = fmaxf(mx0, fmaxf(sf[nt][0], sf[nt][1]));
                mx1 = fmaxf(mx1, fmaxf(sf[nt][2], sf[nt][3]));
            }
            mx0 = fmaxf(mx0, __shfl_xor_sync(0xffffffffu, mx0, 1));
            mx0 = fmaxf(mx0, __shfl_xor_sync(0xffffffffu, mx0, 2));
            mx1 = fmaxf(mx1, __shfl_xor_sync(0xffffffffu, mx1, 1));
            mx1 = fmaxf(mx1, __shfl_xor_sync(0xffffffffu, mx1, 2));

            const float mn0 = fmaxf(m0, mx0), mn1 = fmaxf(m1, mx1);
            const float al0 = exp2f(m0 - mn0), al1 = exp2f(m1 - mn1);
            m0 = mn0; m1 = mn1;

            // P = exp2(S - m) straight to packed half2 via ex2.approx.f16x2
            uint32_t pf[8][2];
#pragma unroll
            for (int nt = 0; nt < 8; nt++) {
                pf[nt][0] = ex2_h2(h2u(__floats2half2_rn(sf[nt][0] - mn0,
                                                         sf[nt][1] - mn0)));
                pf[nt][1] = ex2_h2(h2u(__floats2half2_rn(sf[nt][2] - mn1,
                                                         sf[nt][3] - mn1)));
            }

            // rescale output + row-sum accumulators
#pragma unroll
            for (int nt = 0; nt < 8; nt++) {
                acc[nt][0] *= al0; acc[nt][1] *= al0;
                acc[nt][2] *= al1; acc[nt][3] *= al1;
            }
            lacc[0] *= al0; lacc[1] *= al0;
            lacc[2] *= al1; lacc[3] *= al1;

            // --- O += P @ V ; l += P @ ones (per ks) ---
#pragma unroll
            for (int ks = 0; ks < 4; ks++) {
                uint32_t bf[8][2];
#pragma unroll
                for (int p = 0; p < 4; p++) {
                    const uint32_t addr = vsb + (p * 16 + lm_row) * FH_LDB
                                        + ks * 32 + lm_koff;
                    ldsm_x4(bf[2 * p][0], bf[2 * p][1],
                            bf[2 * p + 1][0], bf[2 * p + 1][1], addr);
                }
                const uint32_t a0 = pf[2 * ks][0];
                const uint32_t a1 = pf[2 * ks][1];
                const uint32_t a2 = pf[2 * ks + 1][0];
                const uint32_t a3 = pf[2 * ks + 1][1];
#pragma unroll
                for (int nt = 0; nt < 8; nt++)
                    mma_f16(acc[nt][0], acc[nt][1], acc[nt][2], acc[nt][3],
                            a0, a1, a2, a3, bf[nt][0], bf[nt][1]);
                mma_f16(lacc[0], lacc[1], lacc[2], lacc[3],
                        a0, a1, a2, a3, ONES_H2, ONES_H2);
            }
        }

        CP_WAIT0();        // next tile's data landed
        __syncthreads();   // stage reuse barrier (1 per tile)
    }

    // --- epilogue (half out for the Wo GEMM) ---
    const float inv0 = 1.0f / lacc[0], inv1 = 1.0f / lacc[2];
    const int r0 = q0 + w * 16 + g;
#pragma unroll
    for (int nt = 0; nt < 8; nt++) {
        const int col = nt * 8 + 2 * q;
        *(__half2*)(O + baseh + (size_t)r0 * DMODEL + col) =
            __floats2half2_rn(acc[nt][0] * inv0, acc[nt][1] * inv0);
        *(__half2*)(O + baseh + (size_t)(r0 + 8) * DMODEL + col) =
            __floats2half2_rn(acc[nt][2] * inv1, acc[nt][3] * inv1);
    }
}

// ---------------------------------------------------------------------------
// Launch
// ---------------------------------------------------------------------------
extern "C" void kernel_launch(void* const* d_in, const int* in_sizes, int n_in,
                              void* d_out, int out_size)
{
    const float* x  = (const float*)d_in[0];
    const float* Wq = (const float*)d_in[1];
    const float* Wk = (const float*)d_in[2];
    const float* Wv = (const float*)d_in[3];
    const float* Wo = (const float*)d_in[4];
    float* out = (float*)d_out;

    __half *xh, *wh, *qb, *kb, *vb, *ab;
    cudaGetSymbolAddress((void**)&xh, g_xh);
    cudaGetSymbolAddress((void**)&wh, g_wh);
    cudaGetSymbolAddress((void**)&qb, g_q);
    cudaGetSymbolAddress((void**)&kb, g_k);
    cudaGetSymbolAddress((void**)&vb, g_v);
    cudaGetSymbolAddress((void**)&ab, g_a);

    cudaFuncSetAttribute(gemm_qkv,
                         cudaFuncAttributeMaxDynamicSharedMemorySize, GEMM_SMEM);
    cudaFuncSetAttribute(gemm_out,
                         cudaFuncAttributeMaxDynamicSharedMemorySize, GEMM_SMEM);
    cudaFuncSetAttribute(flash_attn_f16,
                         cudaFuncAttributeMaxDynamicSharedMemorySize, FA_SMEM);

    // --- prepass: fp32 -> fp16 for x and all weights ---
    f2h<<<MROWS * DMODEL / 2048, 256>>>(x, xh, MROWS * DMODEL);
    f2h4<<<dim3(DMODEL * DMODEL / 2048, 4), 256>>>(Wq, Wk, Wv, Wo, wh);

    // softmax scale folds 1/sqrt(dk) and log2(e) (flash runs in exp2 domain)
    const float qscale = 0.125f * 1.4426950408889634f;

    // --- fused QKV projections (grid.z = 3) ---
    gemm_qkv<<<dim3(DMODEL / 128, MROWS / 128, 3), 256, GEMM_SMEM>>>(
        xh, wh, qb, kb, vb, qscale);

    flash_attn_f16<<<dim3(SEQ / 128, NHEAD, BSZ), 256, FA_SMEM>>>(qb, kb, vb, ab);

    gemm_out<<<dim3(DMODEL / 128, MROWS / 128), 256, GEMM_SMEM>>>(
        ab, wh + (size_t)3 * DMODEL * DMODEL, out);
}